// round 4
// baseline (speedup 1.0000x reference)
#include <cuda_runtime.h>
#include <cstdint>

#define NP      32768
#define NB      128
#define NC      6
#define TOPK    400
#define KEEPK   200
#define NTH     1024
#define CONF_TH 0.5f
#define NMS_TH  0.5f
#define BIGF    1.0e9f
#define NEGF    (-1.0e9f)

// scratch keys: 128 * 32768 * 4B = 16 MB (static device array, no runtime alloc)
__device__ static unsigned int g_keys[(size_t)NB * NP];

__device__ __forceinline__ unsigned int fkey(float x) {
    unsigned int u = __float_as_uint(x);
    return (u & 0x80000000u) ? ~u : (u | 0x80000000u);
}
__device__ __forceinline__ float ikey(unsigned int k) {
    unsigned int u = (k & 0x80000000u) ? (k & 0x7fffffffu) : ~k;
    return __uint_as_float(u);
}

struct __align__(16) SmemT {
    union __align__(16) {
        struct {
            unsigned int hist[4096];   // 16 KB
            unsigned int sscan[1024];  // 4 KB
        } sel;
        unsigned int sup[TOPK * 16];   // 25.6 KB (13 words used, padded to 16)
    } u;
    unsigned long long sortbuf[512];   // 4 KB
    unsigned int selkey[512];
    unsigned int selidx[512];
    float4 cbox[TOPK];                 // 6.4 KB
    float  carea[TOPK];
    float  cscore[TOPK];
    float  clabel[TOPK];
    unsigned int keepw[16];
    int s_bin;
    int s_gt;
    unsigned int s_cnt;
};

// All 1024 threads participate. Finds largest bin d in [0,4096) with
// (count of keys in bins >= d) >= K, returns d and count of keys in bins > d.
__device__ void find_bin(SmemT& s, int K, int& bin_out, int& gt_out) {
    int t = threadIdx.x;
    unsigned int c[4];
    unsigned int sum = 0;
#pragma unroll
    for (int j = 0; j < 4; j++) { c[j] = s.u.sel.hist[4 * t + j]; sum += c[j]; }
    s.u.sel.sscan[t] = sum;
    if (t == 0) s.s_bin = -1;
    __syncthreads();
    // suffix inclusive scan over 1024 thread sums (Hillis-Steele)
    for (int off = 1; off < 1024; off <<= 1) {
        unsigned int v = (t + off < 1024) ? s.u.sel.sscan[t + off] : 0u;
        __syncthreads();
        s.u.sel.sscan[t] += v;
        __syncthreads();
    }
    unsigned int after = s.u.sel.sscan[t] - sum;  // sum over threads > t
    unsigned int run = after;
    int best = -1;
    unsigned int bestgt = 0;
#pragma unroll
    for (int j = 3; j >= 0; j--) {
        unsigned int cnt = c[j];
        if (best < 0 && run + cnt >= (unsigned int)K) { best = 4 * t + j; bestgt = run; }
        run += cnt;
    }
    if (best >= 0) atomicMax(&s.s_bin, best);
    __syncthreads();
    if (best >= 0 && best == s.s_bin) s.s_gt = (int)bestgt;
    __syncthreads();
    bin_out = s.s_bin;
    gt_out = s.s_gt;
}

__global__ __launch_bounds__(NTH, 1)
void box_selector_kernel(const float* __restrict__ pred,
                         const float* __restrict__ priors,
                         float* __restrict__ out) {
    __shared__ SmemT s;
    const int t = threadIdx.x;
    const int b = blockIdx.x;
    const float* pb = pred + (size_t)b * NP * NC;
    unsigned int* keys = g_keys + (size_t)b * NP;

    // ---------- pass 0: keys + 12-bit histogram ----------
    for (int i = t; i < 4096; i += NTH) s.u.sel.hist[i] = 0;
    __syncthreads();
    for (int n = t; n < NP; n += NTH) {
        float2 cf = *reinterpret_cast<const float2*>(pb + n * 6 + 4);
        float sc = fmaxf(cf.x, cf.y);
        float m = (sc > CONF_TH) ? sc : NEGF;
        unsigned int k = fkey(m);
        keys[n] = k;
        unsigned int bin = k >> 20;
        unsigned int mm = __match_any_sync(0xffffffffu, bin);
        int leader = __ffs(mm) - 1;
        if ((t & 31) == leader) atomicAdd(&s.u.sel.hist[bin], (unsigned int)__popc(mm));
    }
    __syncthreads();
    int d1, g1;
    find_bin(s, TOPK, d1, g1);
    int k1 = TOPK - g1;

    // ---------- pass 1: next 12 bits ----------
    __syncthreads();
    for (int i = t; i < 4096; i += NTH) s.u.sel.hist[i] = 0;
    __syncthreads();
    for (int n = t; n < NP; n += NTH) {
        unsigned int k = keys[n];
        if ((int)(k >> 20) == d1) atomicAdd(&s.u.sel.hist[(k >> 8) & 0xfffu], 1u);
    }
    __syncthreads();
    int d2, g2;
    find_bin(s, k1, d2, g2);
    int k2 = k1 - g2;
    unsigned int P24 = ((unsigned int)d1 << 12) | (unsigned int)d2;

    // ---------- pass 2: low byte ----------
    __syncthreads();
    for (int i = t; i < 4096; i += NTH) s.u.sel.hist[i] = 0;
    __syncthreads();
    for (int n = t; n < NP; n += NTH) {
        unsigned int k = keys[n];
        if ((k >> 8) == P24) atomicAdd(&s.u.sel.hist[k & 0xffu], 1u);
    }
    __syncthreads();
    int d3, g3;
    find_bin(s, k2, d3, g3);
    int need = k2 - g3;
    unsigned int KP = (P24 << 8) | (unsigned int)d3;
    int cnt_eq = (int)s.u.sel.hist[d3];
    int cnt_gt = TOPK - need;

    // ---------- gather top-400 (key, idx) ----------
    if (t == 0) s.s_cnt = 0;
    __syncthreads();
    if (cnt_eq == need) {
        for (int n = t; n < NP; n += NTH) {
            unsigned int k = keys[n];
            if (k >= KP) {
                unsigned int p = atomicAdd(&s.s_cnt, 1u);
                s.selkey[p] = k;
                s.selidx[p] = (unsigned int)n;
            }
        }
    } else {
        // strictly-greater: unordered
        for (int n = t; n < NP; n += NTH) {
            unsigned int k = keys[n];
            if (k > KP) {
                unsigned int p = atomicAdd(&s.s_cnt, 1u);
                s.selkey[p] = k;
                s.selidx[p] = (unsigned int)n;
            }
        }
        __syncthreads();
        // equals: take lowest `need` indices, ordered ballot scan (rare path)
        if (t < 32) {
            int taken = 0;
            for (int base = 0; base < NP && taken < need; base += 32) {
                unsigned int k = keys[base + t];
                bool e = (k == KP);
                unsigned int bal = __ballot_sync(0xffffffffu, e);
                int rank = __popc(bal & ((1u << t) - 1u));
                if (e && taken + rank < need) {
                    int slot = cnt_gt + taken + rank;
                    s.selkey[slot] = KP;
                    s.selidx[slot] = (unsigned int)(base + t);
                }
                taken += __popc(bal);
            }
        }
    }
    __syncthreads();

    // ---------- sort 1: descending (key, then lowest idx) -> exact top_k order ----------
    if (t < 512) {
        unsigned long long v = 0ull;
        if (t < TOPK)
            v = ((unsigned long long)s.selkey[t] << 32) | (unsigned int)(~s.selidx[t]);
        s.sortbuf[t] = v;
    }
    __syncthreads();
    for (int kk = 2; kk <= 512; kk <<= 1) {
        for (int j = kk >> 1; j > 0; j >>= 1) {
            if (t < 512) {
                int ixj = t ^ j;
                if (ixj > t) {
                    unsigned long long a = s.sortbuf[t], c = s.sortbuf[ixj];
                    bool desc = ((t & kk) == 0);
                    bool sw = desc ? (a < c) : (a > c);
                    if (sw) { s.sortbuf[t] = c; s.sortbuf[ixj] = a; }
                }
            }
            __syncthreads();
        }
    }

    // ---------- decode 400 candidates ----------
    if (t < 16) s.keepw[t] = (t == 12) ? 0xFFFF0000u : 0u;  // j in [400,416) removed
    if (t < TOPK) {
        unsigned long long v = s.sortbuf[t];
        unsigned int k = (unsigned int)(v >> 32);
        unsigned int idx = ~(unsigned int)v;
        float sc = ikey(k);  // masked score (top_s)
        float4 pr = reinterpret_cast<const float4*>(priors)[idx];
        const float* pp = pb + (size_t)idx * 6;
        float l0 = pp[0], l1 = pp[1], l2 = pp[2], l3 = pp[3];
        float c0 = pp[4], c1 = pp[5];
        float cx = pr.x + l0 * 0.1f * pr.z;
        float cy = pr.y + l1 * 0.1f * pr.w;
        float w  = pr.z * expf(l2 * 0.2f);
        float h  = pr.w * expf(l3 * 0.2f);
        float4 bx = make_float4(cx - 0.5f * w, cy - 0.5f * h, cx + 0.5f * w, cy + 0.5f * h);
        s.cbox[t]   = bx;
        s.carea[t]  = (bx.z - bx.x) * (bx.w - bx.y);
        s.cscore[t] = sc;
        s.clabel[t] = (c1 > c0) ? 1.0f : 0.0f;
    }
    __syncthreads();
    if (t < TOPK) {
        if (!(s.cscore[t] > CONF_TH)) atomicOr(&s.keepw[t >> 5], 1u << (t & 31));
    }
    __syncthreads();

    // ---------- suppression bit matrix: sup[i][w] (j>i, iou>0.5) ----------
    for (int lin = t; lin < TOPK * 16; lin += NTH) {
        int i = lin >> 4;
        int w = lin & 15;
        unsigned int word = 0u;
        if (w < 13) {
            float4 bi = s.cbox[i];
            float ai = s.carea[i];
            int jbase = w * 32;
#pragma unroll 4
            for (int l = 0; l < 32; l++) {
                int j = jbase + l;
                if (j > i && j < TOPK) {
                    float4 bj = s.cbox[j];
                    float iw = fminf(bi.z, bj.z) - fmaxf(bi.x, bj.x);
                    float ih = fminf(bi.w, bj.w) - fmaxf(bi.y, bj.y);
                    iw = fmaxf(iw, 0.0f);
                    ih = fmaxf(ih, 0.0f);
                    float inter = iw * ih;
                    float iou = inter / (ai + s.carea[j] - inter + 1e-12f);
                    if (iou > NMS_TH) word |= (1u << l);
                }
            }
        }
        s.u.sup[lin] = word;
    }
    __syncthreads();

    // ---------- serial greedy NMS reduce (single thread, unrolled, uint4 loads) ----------
    if (t == 0) {
        unsigned int r[13];
#pragma unroll
        for (int w = 0; w < 13; w++) r[w] = s.keepw[w];
        const uint4* sup4 = reinterpret_cast<const uint4*>(s.u.sup);
#pragma unroll
        for (int w = 0; w < 13; w++) {
#pragma unroll
            for (int bb = 0; bb < 32; bb++) {
                int i = w * 32 + bb;
                if (i >= TOPK) break;
                if (!((r[w] >> bb) & 1u)) {
                    uint4 a0 = sup4[i * 4 + 0];
                    uint4 a1 = sup4[i * 4 + 1];
                    uint4 a2 = sup4[i * 4 + 2];
                    uint4 a3 = sup4[i * 4 + 3];
                    r[0]  |= a0.x; r[1]  |= a0.y; r[2]  |= a0.z; r[3]  |= a0.w;
                    r[4]  |= a1.x; r[5]  |= a1.y; r[6]  |= a1.z; r[7]  |= a1.w;
                    r[8]  |= a2.x; r[9]  |= a2.y; r[10] |= a2.z; r[11] |= a2.w;
                    r[12] |= a3.x;
                }
            }
        }
#pragma unroll
        for (int w = 0; w < 13; w++) s.keepw[w] = r[w];
    }
    __syncthreads();

    // ---------- sort 2: ascending (keep ? score : BIG, then position) ----------
    if (t < 512) {
        unsigned long long v = 0xFFFFFFFFFFFFFFFFull;
        if (t < TOPK) {
            bool kp = !((s.keepw[t >> 5] >> (t & 31)) & 1u);
            float skf = kp ? s.cscore[t] : BIGF;           // always positive
            unsigned int sk = __float_as_uint(skf);
            v = ((unsigned long long)sk << 32) | (unsigned int)t;
        }
        s.sortbuf[t] = v;
    }
    __syncthreads();
    for (int kk = 2; kk <= 512; kk <<= 1) {
        for (int j = kk >> 1; j > 0; j >>= 1) {
            if (t < 512) {
                int ixj = t ^ j;
                if (ixj > t) {
                    unsigned long long a = s.sortbuf[t], c = s.sortbuf[ixj];
                    bool asc = ((t & kk) == 0);
                    bool sw = asc ? (a > c) : (a < c);
                    if (sw) { s.sortbuf[t] = c; s.sortbuf[ixj] = a; }
                }
            }
            __syncthreads();
        }
    }

    // ---------- write output ----------
    if (t < KEEPK) {
        unsigned long long v = s.sortbuf[t];
        int c = (int)(unsigned int)(v & 0xffffffffu);
        bool kp = !((s.keepw[c >> 5] >> (c & 31)) & 1u);
        float* o = out + ((size_t)b * KEEPK + t) * 6;
        if (kp) {
            float4 bx = s.cbox[c];
            o[0] = s.clabel[c];
            o[1] = s.cscore[c];
            o[2] = bx.x; o[3] = bx.y; o[4] = bx.z; o[5] = bx.w;
        } else {
            o[0] = 0.0f; o[1] = 0.0f; o[2] = 0.0f;
            o[3] = 0.0f; o[4] = 0.0f; o[5] = 0.0f;
        }
    }
}

extern "C" void kernel_launch(void* const* d_in, const int* in_sizes, int n_in,
                              void* d_out, int out_size) {
    const float* pred = (const float*)d_in[0];
    const float* pri  = (const float*)d_in[1];
    // defensive: identify by size (predictions = B*N*C = 25165824, priors = N*4 = 131072)
    if (n_in >= 2 && in_sizes[0] < in_sizes[1]) {
        const float* tmp = pred; pred = pri; pri = tmp;
    }
    float* out = (float*)d_out;
    box_selector_kernel<<<NB, NTH>>>(pred, pri, out);
}